// round 12
// baseline (speedup 1.0000x reference)
#include <cuda_runtime.h>
#include <cuda_fp16.h>
#include <math.h>
#include <stdint.h>

// ---------------- problem constants ----------------
#define S_LEN  2048
#define BATCH  2
#define DMODEL 768
#define NH     12
#define NKV    4
#define HDIM   64
#define FFDIM  3072
#define NLAYER 2
#define M_TOK  (BATCH * S_LEN)   // 4096 tokens
#define KVD    (NKV * HDIM)      // 256

// ---------------- scratch (device globals; no allocation allowed) ----------
__device__ __align__(16) __half g_h    [M_TOK * DMODEL];
__device__ __align__(16) __half g_q    [M_TOK * DMODEL];
__device__ __align__(16) __half g_k    [M_TOK * KVD];
__device__ __align__(16) __half g_v    [M_TOK * KVD];
__device__ __align__(16) __half g_att  [M_TOK * DMODEL];
__device__ __align__(16) __half g_gate [M_TOK * FFDIM];
__device__ __align__(16) __half g_gate2[M_TOK * FFDIM];
__device__ __align__(16) float  g_x1   [M_TOK * DMODEL];
__device__ __align__(16) float  g_x2   [M_TOK * DMODEL];
__device__ __align__(16) float  g_cosT [S_LEN * 32];
__device__ __align__(16) float  g_sinT [S_LEN * 32];
// fp16 transposed weights [N][K] per layer
__device__ __align__(16) __half g_hWq[NLAYER * DMODEL * DMODEL];
__device__ __align__(16) __half g_hWk[NLAYER * KVD * DMODEL];
__device__ __align__(16) __half g_hWv[NLAYER * KVD * DMODEL];
__device__ __align__(16) __half g_hWo[NLAYER * DMODEL * DMODEL];
__device__ __align__(16) __half g_hw0[NLAYER * FFDIM * DMODEL];
__device__ __align__(16) __half g_hw1[NLAYER * FFDIM * DMODEL];
__device__ __align__(16) __half g_hw2[NLAYER * DMODEL * FFDIM];

// ---------------- helpers ----------------
__device__ __forceinline__ void mma_f16(float (&c)[4],
                                        uint32_t a0, uint32_t a1, uint32_t a2, uint32_t a3,
                                        uint32_t b0, uint32_t b1) {
    asm volatile(
        "mma.sync.aligned.m16n8k16.row.col.f32.f16.f16.f32 "
        "{%0,%1,%2,%3}, {%4,%5,%6,%7}, {%8,%9}, {%0,%1,%2,%3};"
        : "+f"(c[0]), "+f"(c[1]), "+f"(c[2]), "+f"(c[3])
        : "r"(a0), "r"(a1), "r"(a2), "r"(a3), "r"(b0), "r"(b1));
}
__device__ __forceinline__ void ldsm_x4(uint32_t& r0, uint32_t& r1,
                                        uint32_t& r2, uint32_t& r3, uint32_t addr) {
    asm volatile("ldmatrix.sync.aligned.m8n8.x4.shared.b16 {%0,%1,%2,%3}, [%4];"
                 : "=r"(r0), "=r"(r1), "=r"(r2), "=r"(r3) : "r"(addr));
}
__device__ __forceinline__ void cpa16(uint32_t d, const void* s) {
    asm volatile("cp.async.cg.shared.global [%0], [%1], 16;" :: "r"(d), "l"(s));
}
__device__ __forceinline__ void cpcommit() { asm volatile("cp.async.commit_group;"); }
__device__ __forceinline__ void cpwait1()  { asm volatile("cp.async.wait_group 1;"); }
__device__ __forceinline__ void cpwait0()  { asm volatile("cp.async.wait_group 0;"); }

// ---------------- RoPE tables ----------------
__global__ void rope_table_kernel(float* __restrict__ cosT, float* __restrict__ sinT) {
    int idx = blockIdx.x * blockDim.x + threadIdx.x;
    if (idx >= S_LEN * 32) return;
    int p = idx >> 5, i = idx & 31;
    double f  = exp(-((double)(2 * i) / 64.0) * log(10000.0));
    float ang = (float)p * (float)f;
    cosT[idx] = (float)cos((double)ang);
    sinT[idx] = (float)sin((double)ang);
}

// ---------------- weight transpose + fp16 convert: src[K][N] -> dst[N][K] --
__global__ void w_t_h_kernel(const float* __restrict__ src, __half* __restrict__ dst,
                             int K, int N) {
    __shared__ float tile[32][33];
    int l = blockIdx.z;
    src += (size_t)l * K * N;
    dst += (size_t)l * K * N;
    int nb = blockIdx.x * 32, kb = blockIdx.y * 32;
    int tx = threadIdx.x, ty = threadIdx.y;   // 32 x 8
#pragma unroll
    for (int i = 0; i < 4; i++)
        tile[ty + 8 * i][tx] = src[(size_t)(kb + ty + 8 * i) * N + nb + tx];
    __syncthreads();
#pragma unroll
    for (int i = 0; i < 4; i++)
        dst[(size_t)(nb + ty + 8 * i) * K + kb + tx] = __float2half_rn(tile[tx][ty + 8 * i]);
}

// ---------------- RMSNorm ----------------
__global__ void rmsnorm_kernel(const float* __restrict__ x,
                               const float* __restrict__ w,
                               __half* __restrict__ oh,
                               float* __restrict__ of) {
    int row = blockIdx.x;
    const float* xr = x + (size_t)row * DMODEL;
    float v[3];
    float s = 0.f;
#pragma unroll
    for (int t = 0; t < 3; t++) {
        v[t] = xr[threadIdx.x + t * 256];
        s += v[t] * v[t];
    }
#pragma unroll
    for (int off = 16; off > 0; off >>= 1) s += __shfl_xor_sync(0xffffffffu, s, off);
    __shared__ float red[8];
    if ((threadIdx.x & 31) == 0) red[threadIdx.x >> 5] = s;
    __syncthreads();
    float tot = 0.f;
#pragma unroll
    for (int i = 0; i < 8; i++) tot += red[i];
    float scale = rsqrtf(tot * (1.0f / (float)DMODEL) + 1e-6f);
    if (oh) {
        __half* orow = oh + (size_t)row * DMODEL;
#pragma unroll
        for (int t = 0; t < 3; t++) {
            int c = threadIdx.x + t * 256;
            orow[c] = __float2half_rn(v[t] * scale * w[c]);
        }
    } else {
        float* orow = of + (size_t)row * DMODEL;
#pragma unroll
        for (int t = 0; t < 3; t++) {
            int c = threadIdx.x + t * 256;
            orow[c] = v[t] * scale * w[c];
        }
    }
}

// ---------------- shared GEMM mainloop constants ----------------
// 128x128x32 CTA tile, 4 warps (2x2), 64x64 warp tile.
#define KT   32
#define STG  3
#define AST  40
#define BST  40
#define GEMM_SMEM ((STG * 128 * AST + STG * 128 * BST) * 2)   // 61440 bytes
#define GATE_SMEM ((2 * 128 * AST + STG * 128 * BST) * 2)     // 51200 bytes

// ---------------- fused QKV GEMM (+RoPE epilogue for Q,K) ------------------
__global__ void __launch_bounds__(128, 2) qkv_gemm_kernel(
    const __half* __restrict__ A,
    const __half* __restrict__ Bq, const __half* __restrict__ Bk,
    const __half* __restrict__ Bv,
    __half* __restrict__ q, __half* __restrict__ k, __half* __restrict__ v,
    const float* __restrict__ cosT, const float* __restrict__ sinT) {
    const int bx = blockIdx.x;
    const __half* Bt;
    __half* O;
    int colB, strideO, doRope;
    if (bx < 6)      { Bt = Bq; O = q; colB = bx * 128;       strideO = DMODEL; doRope = 1; }
    else if (bx < 8) { Bt = Bk; O = k; colB = (bx - 6) * 128; strideO = KVD;    doRope = 1; }
    else             { Bt = Bv; O = v; colB = (bx - 8) * 128; strideO = KVD;    doRope = 0; }

    extern __shared__ __half sm[];
    __half* Asm = sm;
    __half* Bsm = sm + STG * 128 * AST;
    uint32_t aBase = (uint32_t)__cvta_generic_to_shared(Asm);
    uint32_t bBase = (uint32_t)__cvta_generic_to_shared(Bsm);

    const int tid  = threadIdx.x;
    const int lane = tid & 31;
    const int warp = tid >> 5;
    const int wm   = warp & 1;     // rows wm*64
    const int wn   = warp >> 1;    // cols wn*64
    const int rowBase = blockIdx.y * 128;
    const int lq = lane >> 2;
    const int lr = lane & 3;
    const int K = DMODEL;

    float acc[4][8][4];
#pragma unroll
    for (int i = 0; i < 4; i++)
#pragma unroll
        for (int j = 0; j < 8; j++)
#pragma unroll
            for (int t = 0; t < 4; t++) acc[i][j][t] = 0.f;

    const int T = K / KT;

    auto stage = [&](int s, int kt) {
#pragma unroll
        for (int c0 = 0; c0 < 4; c0++) {
            int c = tid + c0 * 128;
            int r = c >> 2, k8 = (c & 3) * 8;
            cpa16(aBase + (uint32_t)(s * 128 * AST + r * AST + k8) * 2,
                  A  + (size_t)(rowBase + r) * K + kt * KT + k8);
            cpa16(bBase + (uint32_t)(s * 128 * BST + r * BST + k8) * 2,
                  Bt + (size_t)(colB + r) * K + kt * KT + k8);
        }
    };

    stage(0, 0); cpcommit();
    stage(1, 1); cpcommit();

    const int aRowSel = lane & 15;
    const int aKSel   = (lane >> 4) << 3;
    const int bRowSel = (lane & 7) + ((lane >> 4) << 3);
    const int bKSel   = ((lane >> 3) & 1) << 3;

    for (int t = 0; t < T; t++) {
        cpwait1();
        __syncthreads();
        if (t + 2 < T) stage((t + 2) % STG, t + 2);
        cpcommit();

        const uint32_t aTile = aBase + (uint32_t)((t % STG) * 128 * AST) * 2;
        const uint32_t bTile = bBase + (uint32_t)((t % STG) * 128 * BST) * 2;
#pragma unroll
        for (int kf = 0; kf < 2; kf++) {
            const int k0 = kf * 16;
            uint32_t af[4][4];
#pragma unroll
            for (int mf = 0; mf < 4; mf++) {
                int r0 = wm * 64 + mf * 16;
                ldsm_x4(af[mf][0], af[mf][1], af[mf][2], af[mf][3],
                        aTile + (uint32_t)((r0 + aRowSel) * AST + k0 + aKSel) * 2);
            }
#pragma unroll
            for (int ng = 0; ng < 4; ng++) {
                int c0 = wn * 64 + ng * 16;
                uint32_t b0, b1, b2, b3;
                ldsm_x4(b0, b1, b2, b3,
                        bTile + (uint32_t)((c0 + bRowSel) * BST + k0 + bKSel) * 2);
#pragma unroll
                for (int mf = 0; mf < 4; mf++) {
                    mma_f16(acc[mf][2 * ng],     af[mf][0], af[mf][1], af[mf][2], af[mf][3], b0, b1);
                    mma_f16(acc[mf][2 * ng + 1], af[mf][0], af[mf][1], af[mf][2], af[mf][3], b2, b3);
                }
            }
        }
    }
    __syncthreads();

#pragma unroll
    for (int mf = 0; mf < 4; mf++) {
        int row0 = rowBase + wm * 64 + mf * 16 + lq;
#pragma unroll
        for (int nf = 0; nf < 8; nf++) {
            int col = colB + wn * 64 + nf * 8 + 2 * lr;
#pragma unroll
            for (int hh = 0; hh < 2; hh++) {
                int row = row0 + hh * 8;
                float v0 = acc[mf][nf][hh * 2];
                float v1 = acc[mf][nf][hh * 2 + 1];
                if (doRope) {
                    int i = (col & 63) >> 1;
                    int pos = row & (S_LEN - 1);
                    float c = cosT[pos * 32 + i];
                    float s = sinT[pos * 32 + i];
                    float r0 = v0 * c - v1 * s;
                    float r1 = v0 * s + v1 * c;
                    v0 = r0; v1 = r1;
                }
                *(__half2*)(O + (size_t)row * strideO + col) = __floats2half2_rn(v0, v1);
            }
        }
    }
}

// ---------------- generic FP16 GEMM ----------------
// mode: 0 plain(h16), 1 silu(h16), 3 acc+aux32(f32),
//       5 dual: z==0 -> silu -> O0 ; z==1 -> plain -> O1
__global__ void __launch_bounds__(128, 2) gemm_f16_kernel(
    const __half* __restrict__ A,
    const __half* __restrict__ B0t, const __half* __restrict__ B1t,
    const void* __restrict__ aux,
    void* __restrict__ O0, void* __restrict__ O1,
    int N, int K, int mode) {
    const __half* Bt = blockIdx.z ? B1t : B0t;
    void*         O  = blockIdx.z ? O1 : O0;
    extern __shared__ __half sm[];
    __half* Asm = sm;
    __half* Bsm = sm + STG * 128 * AST;
    uint32_t aBase = (uint32_t)__cvta_generic_to_shared(Asm);
    uint32_t bBase = (uint32_t)__cvta_generic_to_shared(Bsm);

    const int tid  = threadIdx.x;
    const int lane = tid & 31;
    const int warp = tid >> 5;
    const int wm   = warp & 1;
    const int wn   = warp >> 1;
    const int rowBase = blockIdx.y * 128;
    const int colBase = blockIdx.x * 128;
    const int lq = lane >> 2;
    const int lr = lane & 3;
    const int doSilu = (mode == 1) || (mode == 5 && blockIdx.z == 0);

    float acc[4][8][4];
#pragma unroll
    for (int i = 0; i < 4; i++)
#pragma unroll
        for (int j = 0; j < 8; j++)
#pragma unroll
            for (int t = 0; t < 4; t++) acc[i][j][t] = 0.f;

    const int T = K / KT;

    auto stage = [&](int s, int kt) {
#pragma unroll
        for (int c0 = 0; c0 < 4; c0++) {
            int c = tid + c0 * 128;
            int r = c >> 2, k8 = (c & 3) * 8;
            cpa16(aBase + (uint32_t)(s * 128 * AST + r * AST + k8) * 2,
                  A  + (size_t)(rowBase + r) * K + kt * KT + k8);
            cpa16(bBase + (uint32_t)(s * 128 * BST + r * BST + k8) * 2,
                  Bt + (size_t)(colBase + r) * K + kt * KT + k8);
        }
    };

    stage(0, 0); cpcommit();
    stage(1, 1); cpcommit();

    const int aRowSel = lane & 15;
    const int aKSel   = (lane >> 4) << 3;
    const int bRowSel = (lane & 7) + ((lane >> 4) << 3);
    const int bKSel   = ((lane >> 3) & 1) << 3;

    for (int t = 0; t < T; t++) {
        cpwait1();
        __syncthreads();
        if (t + 2 < T) stage((t + 2) % STG, t + 2);
        cpcommit();

        const uint32_t aTile = aBase + (uint32_t)((t % STG) * 128 * AST) * 2;
        const uint32_t bTile = bBase + (uint32_t)((t % STG) * 128 * BST) * 2;
#pragma unroll
        for (int kf = 0; kf < 2; kf++) {
            const int k0 = kf * 16;
            uint32_t af[4][4];
#pragma unroll
            for (int mf = 0; mf < 4; mf++) {
                int r0 = wm * 64 + mf * 16;
                ldsm_x4(af[mf][0], af[mf][1], af[mf][2], af[mf][3],
                        aTile + (uint32_t)((r0 + aRowSel) * AST + k0 + aKSel) * 2);
            }
#pragma unroll
            for (int ng = 0; ng < 4; ng++) {
                int c0 = wn * 64 + ng * 16;
                uint32_t b0, b1, b2, b3;
                ldsm_x4(b0, b1, b2, b3,
                        bTile + (uint32_t)((c0 + bRowSel) * BST + k0 + bKSel) * 2);
#pragma unroll
                for (int mf = 0; mf < 4; mf++) {
                    mma_f16(acc[mf][2 * ng],     af[mf][0], af[mf][1], af[mf][2], af[mf][3], b0, b1);
                    mma_f16(acc[mf][2 * ng + 1], af[mf][0], af[mf][1], af[mf][2], af[mf][3], b2, b3);
                }
            }
        }
    }
    __syncthreads();

#pragma unroll
    for (int mf = 0; mf < 4; mf++) {
        int row0 = rowBase + wm * 64 + mf * 16 + lq;
#pragma unroll
        for (int nf = 0; nf < 8; nf++) {
            int col = colBase + wn * 64 + nf * 8 + 2 * lr;
#pragma unroll
            for (int hh = 0; hh < 2; hh++) {
                int row = row0 + hh * 8;
                size_t idx = (size_t)row * N + col;
                float v0 = acc[mf][nf][hh * 2];
                float v1 = acc[mf][nf][hh * 2 + 1];
                if (mode == 3) {
                    float2 a2 = *(const float2*)((const float*)aux + idx);
                    *(float2*)((float*)O + idx) = make_float2(v0 + a2.x, v1 + a2.y);
                } else {
                    if (doSilu) {
                        v0 = v0 / (1.f + __expf(-v0));
                        v1 = v1 / (1.f + __expf(-v1));
                    }
                    *(__half2*)((__half*)O + idx) = __floats2half2_rn(v0, v1);
                }
            }
        }
    }
}

// ---------------- gated GEMM: O = (GA .* GB) @ Bt^T + aux (fp32 out) -------
__global__ void __launch_bounds__(128, 2) gemm_gate_kernel(
    const __half* __restrict__ GA, const __half* __restrict__ GB,
    const __half* __restrict__ Bt, const float* __restrict__ aux,
    float* __restrict__ O, int N, int K) {
    extern __shared__ __half sm[];
    __half* Asm = sm;                      // [2][128][AST]
    __half* Bsm = sm + 2 * 128 * AST;      // [STG][128][BST]
    uint32_t aBase = (uint32_t)__cvta_generic_to_shared(Asm);
    uint32_t bBase = (uint32_t)__cvta_generic_to_shared(Bsm);

    const int tid  = threadIdx.x;
    const int lane = tid & 31;
    const int warp = tid >> 5;
    const int wm   = warp & 1;
    const int wn   = warp >> 1;
    const int rowBase = blockIdx.y * 128;
    const int colBase = blockIdx.x * 128;
    const int lq = lane >> 2;
    const int lr = lane & 3;

    float acc[4][8][4];
#pragma unroll
    for (int i = 0; i < 4; i++)
#pragma unroll
        for (int j = 0; j < 8; j++)
#pragma unroll
            for (int t = 0; t < 4; t++) acc[i][j][t] = 0.f;

    const int T = K / KT;
    uint4 ra[4];

    auto loadA = [&](int kt) {
#pragma unroll
        for (int c0 = 0; c0 < 4; c0++) {
            int c = tid + c0 * 128;
            int r = c >> 2, k8 = (c & 3) * 8;
            size_t off = (size_t)(rowBase + r) * K + kt * KT + k8;
            uint4 a4 = *(const uint4*)(GA + off);
            uint4 b4 = *(const uint4*)(GB + off);
            __half2* ah = (__half2*)&a4;
            const __half2* bh = (const __half2*)&b4;
            ah[0] = __hmul2(ah[0], bh[0]);
            ah[1] = __hmul2(ah[1], bh[1]);
            ah[2] = __hmul2(ah[2], bh[2]);
            ah[3] = __hmul2(ah[3], bh[3]);
            ra[c0] = a4;
        }
    };
    auto stsA = [&](int buf) {
#pragma unroll
        for (int c0 = 0; c0 < 4; c0++) {
            int c = tid + c0 * 128;
            int r = c >> 2, k8 = (c & 3) * 8;
            *(uint4*)(Asm + buf * 128 * AST + r * AST + k8) = ra[c0];
        }
    };
    auto stageB = [&](int s, int kt) {
#pragma unroll
        for (int c0 = 0; c0 < 4; c0++) {
            int c = tid + c0 * 128;
            int r = c >> 2, k8 = (c & 3) * 8;
            cpa16(bBase + (uint32_t)(s * 128 * BST + r * BST + k8) * 2,
                  Bt + (size_t)(colBase + r) * K + kt * KT + k8);
        }
    };

    loadA(0); stsA(0);
    stageB(0, 0); cpcommit();
    stageB(1, 1); cpcommit();
    if (T > 1) loadA(1);

    const int aRowSel = lane & 15;
    const int aKSel   = (lane >> 4) << 3;
    const int bRowSel = (lane & 7) + ((lane >> 4) << 3);
    const int bKSel   = ((lane >> 3) & 1) << 3;

    for (int t = 0; t < T; t++) {
        cpwait1();
        __syncthreads();
        if (t + 2 < T) stageB((t + 2) % STG, t + 2);
        cpcommit();

        const uint32_t aTile = aBase + (uint32_t)((t & 1) * 128 * AST) * 2;
        const uint32_t bTile = bBase + (uint32_t)((t % STG) * 128 * BST) * 2;
#pragma unroll
        for (int kf = 0; kf < 2; kf++) {
            const int k0 = kf * 16;
            uint32_t af[4][4];
#pragma unroll
            for (int mf = 0; mf < 4; mf++) {
                int r0 = wm * 64 + mf * 16;
                ldsm_x4(af[mf][0], af[mf][1], af[mf][2], af[mf][3],
                        aTile + (uint32_t)((r0 + aRowSel) * AST + k0 + aKSel) * 2);
            }
#pragma unroll
            for (int ng = 0; ng < 4; ng++) {
                int c0 = wn * 64 + ng * 16;
                uint32_t b0, b1, b2, b3;
                ldsm_x4(b0, b1, b2, b3,
                        bTile + (uint32_t)((c0 + bRowSel) * BST + k0 + bKSel) * 2);
#pragma unroll
                for (int mf = 0; mf < 4; mf++) {
                    mma_f16(acc[mf][2 * ng],     af[mf][0], af[mf][1], af[mf][2], af[mf][3], b0, b1);
                    mma_f16(acc[mf][2 * ng + 1], af[mf][0], af[mf][1], af[mf][2], af[mf][3], b2, b3);
                }
            }
        }
        if (t + 1 < T) {
            stsA((t + 1) & 1);
            if (t + 2 < T) loadA(t + 2);
        }
    }
    __syncthreads();

#pragma unroll
    for (int mf = 0; mf < 4; mf++) {
        int row0 = rowBase + wm * 64 + mf * 16 + lq;
#pragma unroll
        for (int nf = 0; nf < 8; nf++) {
            int col = colBase + wn * 64 + nf * 8 + 2 * lr;
#pragma unroll
            for (int hh = 0; hh < 2; hh++) {
                int row = row0 + hh * 8;
                size_t idx = (size_t)row * N + col;
                float2 a2 = *(const float2*)(aux + idx);
                *(float2*)(O + idx) = make_float2(acc[mf][nf][hh * 2] + a2.x,
                                                  acc[mf][nf][hh * 2 + 1] + a2.y);
            }
        }
    }
}

// ---------------- Flash attention, FP16 mma (causal, GQA), cp.async K/V ----
#define VST 72
#define FLASH_SMEM (6 * 64 * VST * 2)

__global__ void __launch_bounds__(128) flash_f16_kernel(
    const __half* __restrict__ q, const __half* __restrict__ k,
    const __half* __restrict__ v, __half* __restrict__ o) {
    extern __shared__ __half smh[];
    __half* Qh = smh;
    __half* Kh = smh + 64 * VST;
    __half* Vh = smh + 3 * 64 * VST;
    __half* Ph = smh + 5 * 64 * VST;
    uint32_t qhBase = (uint32_t)__cvta_generic_to_shared(Qh);
    uint32_t kBase  = (uint32_t)__cvta_generic_to_shared(Kh);
    uint32_t vBase  = (uint32_t)__cvta_generic_to_shared(Vh);
    uint32_t phBase = (uint32_t)__cvta_generic_to_shared(Ph);

    const int qb  = (gridDim.x - 1) - blockIdx.x;
    const int bh  = blockIdx.y;
    const int b   = bh / NH;
    const int h   = bh % NH;
    const int kvh = h / (NH / NKV);
    const int tid  = threadIdx.x;
    const int lane = tid & 31;
    const int warp = tid >> 5;
    const int lq = lane >> 2;
    const int lr = lane & 3;

    for (int t = tid; t < 64 * 8; t += 128) {
        int r = t >> 3, c8 = (t & 7) * 8;
        uint4 raw = *(const uint4*)(q + ((size_t)((b * S_LEN + qb * 64 + r) * NH + h)) * HDIM + c8);
        *(uint4*)(Qh + r * VST + c8) = raw;
    }

    auto stageKV = [&](int buf, int kb) {
        for (int t = tid; t < 64 * 8; t += 128) {
            int r = t >> 3, c8 = (t & 7) * 8;
            size_t goff = ((size_t)((b * S_LEN + kb * 64 + r) * NKV + kvh)) * HDIM + c8;
            uint32_t soff = (uint32_t)(buf * 64 * VST + r * VST + c8) * 2;
            cpa16(kBase + soff, k + goff);
            cpa16(vBase + soff, v + goff);
        }
    };
    stageKV(0, 0); cpcommit();

    const int wrow = warp * 16;
    const int r0l = wrow + lq;
    const int qrow0 = qb * 64 + r0l;
    const int qrow1 = qrow0 + 8;

    const int aRowSel = lane & 15;
    const int aKSel   = (lane >> 4) << 3;
    const int bRowSel = (lane & 7) + ((lane >> 4) << 3);
    const int bKSel   = ((lane >> 3) & 1) << 3;

    float m0 = -1e30f, m1 = -1e30f, l0 = 0.f, l1 = 0.f;
    float oacc[8][4];
#pragma unroll
    for (int nf = 0; nf < 8; nf++)
#pragma unroll
        for (int t = 0; t < 4; t++) oacc[nf][t] = 0.f;

    for (int kb = 0; kb <= qb; kb++) {
        const int buf = kb & 1;
        cpwait0();
        __syncthreads();
        if (kb + 1 <= qb) { stageKV(buf ^ 1, kb + 1); cpcommit(); }

        const uint32_t kTile = kBase + (uint32_t)(buf * 64 * VST) * 2;

        float sacc[8][4];
#pragma unroll
        for (int nf = 0; nf < 8; nf++)
#pragma unroll
            for (int t = 0; t < 4; t++) sacc[nf][t] = 0.f;

#pragma unroll
        for (int kf = 0; kf < 4; kf++) {
            const int k0 = kf * 16;
            uint32_t a0, a1, a2, a3;
            ldsm_x4(a0, a1, a2, a3,
                    qhBase + (uint32_t)((wrow + aRowSel) * VST + k0 + aKSel) * 2);
#pragma unroll
            for (int ng = 0; ng < 4; ng++) {
                int c0 = ng * 16;
                uint32_t b0, b1, b2, b3;
                ldsm_x4(b0, b1, b2, b3,
                        kTile + (uint32_t)((c0 + bRowSel) * VST + k0 + bKSel) * 2);
                mma_f16(sacc[2 * ng],     a0, a1, a2, a3, b0, b1);
                mma_f16(sacc[2 * ng + 1], a0, a1, a2, a3, b2, b3);
            }
        }

        const bool diag = (kb == qb);
        float rmax0 = -1e30f, rmax1 = -1e30f;
#pragma unroll
        for (int nf = 0; nf < 8; nf++) {
            int jc = kb * 64 + nf * 8 + 2 * lr;
            float s0 = sacc[nf][0] * 0.125f;
            float s1 = sacc[nf][1] * 0.125f;
            float s2 = sacc[nf][2] * 0.125f;
            float s3 = sacc[nf][3] * 0.125f;
            if (diag) {
                if (jc     > qrow0) s0 = -1e30f;
                if (jc + 1 > qrow0) s1 = -1e30f;
                if (jc     > qrow1) s2 = -1e30f;
                if (jc + 1 > qrow1) s3 = -1e30f;
            }
            sacc[nf][0] = s0; sacc[nf][1] = s1; sacc[nf][2] = s2; sacc[nf][3] = s3;
            rmax0 = fmaxf(rmax0, fmaxf(s0, s1));
            rmax1 = fmaxf(rmax1, fmaxf(s2, s3));
        }
        rmax0 = fmaxf(rmax0, __shfl_xor_sync(0xffffffffu, rmax0, 1));
        rmax0 = fmaxf(rmax0, __shfl_xor_sync(0xffffffffu, rmax0, 2));
        rmax1 = fmaxf(rmax1, __shfl_xor_sync(0xffffffffu, rmax1, 1));
        rmax1 = fmaxf(rmax1, __shfl_xor_sync(0xffffffffu, rmax1, 2));

        float mn0 = fmaxf(m0, rmax0);
        float mn1 = fmaxf(m1, rmax1);
        float alpha0 = __expf(m0 - mn0);
        float alpha1 = __expf(m1 - mn1);
        m0 = mn0; m1 = mn1;

        float rsum0 = 0.f, rsum1 = 0.f;
#pragma unroll
        for (int nf = 0; nf < 8; nf++) {
            float p0 = __expf(sacc[nf][0] - mn0);
            float p1 = __expf(sacc[nf][1] - mn0);
            float p2 = __expf(sacc[nf][2] - mn1);
            float p3 = __expf(sacc[nf][3] - mn1);
            sacc[nf][0] = p0; sacc[nf][1] = p1; sacc[nf][2] = p2; sacc[nf][3] = p3;
            rsum0 += p0 + p1;
            rsum1 += p2 + p3;
        }
        rsum0 += __shfl_xor_sync(0xffffffffu, rsum0, 1);
        rsum0 += __shfl_xor_sync(0xffffffffu, rsum0, 2);
        rsum1 += __shfl_xor_sync(0xffffffffu, rsum1, 1);
        rsum1 += __shfl_xor_sync(0xffffffffu, rsum1, 2);
        l0 = l0 * alpha0 + rsum0;
        l1 = l1 * alpha1 + rsum1;

#pragma unroll
        for (int nf = 0; nf < 8; nf++) {
            oacc[nf][0] *= alpha0; oacc[nf][1] *= alpha0;
            oacc[nf][2] *= alpha1; oacc[nf][3] *= alpha1;
        }

#pragma unroll
        for (int nf = 0; nf < 8; nf++) {
            int pc = nf * 8 + 2 * lr;
            *(__half2*)(Ph + r0l * VST + pc)       = __floats2half2_rn(sacc[nf][0], sacc[nf][1]);
            *(__half2*)(Ph + (r0l + 8) * VST + pc) = __floats2half2_rn(sacc[nf][2], sacc[nf][3]);
        }
        __syncwarp();

        const uint32_t vTile = vBase + (uint32_t)(buf * 64 * VST) * 2;
#pragma unroll
        for (int kf = 0; kf < 4; kf++) {
            const int k0 = kf * 16;
            uint32_t a0, a1, a2, a3;
            ldsm_x4(a0, a1, a2, a3,
                    phBase + (uint32_t)((wrow + aRowSel) * VST + k0 + aKSel) * 2);
#pragma unroll
            for (int np = 0; np < 4; np++) {
                const int d0 = np * 16;
                uint32_t addr = vTile +
                    (uint32_t)((k0 + (lane & 15)) * VST + d0 + ((lane & 16) >> 1)) * 2;
                uint32_t bb0, bb1, bb2, bb3;
                asm volatile(
                    "ldmatrix.sync.aligned.m8n8.x4.trans.shared.b16 {%0,%1,%2,%3}, [%4];"
                    : "=r"(bb0), "=r"(bb1), "=r"(bb2), "=r"(bb3) : "r"(addr));
                mma_f16(oacc[2 * np],     a0, a1, a2, a3, bb0, bb1);
                mma_f16(oacc[2 * np + 1], a0, a1, a2, a3, bb2, bb3);
            }
        }
    }

    float inv0 = 1.f / l0;
    float inv1 = 1.f / l1;
    int grow0 = b * S_LEN + qrow0;
    int grow1 = b * S_LEN + qrow1;
#pragma unroll
    for (int nf = 0; nf < 8; nf++) {
        int col = nf * 8 + 2 * lr;
        *(__half2*)(o + ((size_t)(grow0 * NH + h)) * HDIM + col) =
            __floats2half2_rn(oacc[nf][0] * inv0, oacc[nf][1] * inv0);
        *(__half2*)(o + ((size_t)(grow1 * NH + h)) * HDIM + col) =
            __floats2half2_rn(oacc[nf][2] * inv1, oacc[nf][3] * inv1);
    }
}

// ---------------- launch ----------------
extern "C" void kernel_launch(void* const* d_in, const int* in_sizes, int n_in,
                              void* d_out, int out_size) {
    const float* x  = (const float*)d_in[0];
    const float* Wq = (const float*)d_in[1];
    const float* Wk = (const float*)d_in[2];
    const float* Wv = (const float*)d_in[3];
    const float* Wo = (const float*)d_in[4];
    const float* an = (const float*)d_in[5];
    const float* w0 = (const float*)d_in[6];
    const float* w1 = (const float*)d_in[7];
    const float* w2 = (const float*)d_in[8];
    const float* sn = (const float*)d_in[9];
    const float* on = (const float*)d_in[10];
    float* out = (float*)d_out;

    __half *h, *q, *k, *v, *att, *gate, *gate2;
    __half *hWq, *hWk, *hWv, *hWo, *hw0, *hw1, *hw2;
    float *x1, *x2, *cosT, *sinT;
    cudaGetSymbolAddress((void**)&h,     g_h);
    cudaGetSymbolAddress((void**)&q,     g_q);
    cudaGetSymbolAddress((void**)&k,     g_k);
    cudaGetSymbolAddress((void**)&v,     g_v);
    cudaGetSymbolAddress((void**)&att,   g_att);
    cudaGetSymbolAddress((void**)&gate,  g_gate);
    cudaGetSymbolAddress((void**)&gate2, g_gate2);
    cudaGetSymbolAddress((void**)&x1,    g_x1);
    cudaGetSymbolAddress((void**)&x2,    g_x2);
    cudaGetSymbolAddress((void**)&cosT,  g_cosT);
    cudaGetSymbolAddress((void**)&sinT,  g_sinT);
    cudaGetSymbolAddress((void**)&hWq,   g_hWq);
    cudaGetSymbolAddress((void**)&hWk,   g_hWk);
    cudaGetSymbolAddress((void**)&hWv,   g_hWv);
    cudaGetSymbolAddress((void**)&hWo,   g_hWo);
    cudaGetSymbolAddress((void**)&hw0,   g_hw0);
    cudaGetSymbolAddress((void**)&hw1,   g_hw1);
    cudaGetSymbolAddress((void**)&hw2,   g_hw2);

    cudaFuncSetAttribute(flash_f16_kernel,
                         cudaFuncAttributeMaxDynamicSharedMemorySize, FLASH_SMEM);
    cudaFuncSetAttribute(gemm_f16_kernel,
                         cudaFuncAttributeMaxDynamicSharedMemorySize, GEMM_SMEM);
    cudaFuncSetAttribute(qkv_gemm_kernel,
                         cudaFuncAttributeMaxDynamicSharedMemorySize, GEMM_SMEM);
    cudaFuncSetAttribute(gemm_gate_kernel,
                         cudaFuncAttributeMaxDynamicSharedMemorySize, GATE_SMEM);

    static cudaStream_t s2 = nullptr;
    static cudaEvent_t ev0, ev1, ev2;
    if (!s2) {
        cudaStreamCreateWithFlags(&s2, cudaStreamNonBlocking);
        cudaEventCreateWithFlags(&ev0, cudaEventDisableTiming);
        cudaEventCreateWithFlags(&ev1, cudaEventDisableTiming);
        cudaEventCreateWithFlags(&ev2, cudaEventDisableTiming);
    }

    const dim3 tb(32, 8);
    const dim3 gQKV (10, M_TOK / 128, 1);
    const dim3 gN768(DMODEL / 128, M_TOK / 128, 1);
    const dim3 gFF2 (FFDIM / 128,  M_TOK / 128, 2);

    cudaEventRecord(ev0, 0);
    cudaStreamWaitEvent(s2, ev0, 0);

    rope_table_kernel<<<(S_LEN * 32 + 255) / 256, 256>>>(cosT, sinT);
    w_t_h_kernel<<<dim3(DMODEL / 32, DMODEL / 32, NLAYER), tb, 0, s2>>>(Wq, hWq, DMODEL, DMODEL);
    w_t_h_kernel<<<dim3(KVD / 32,    DMODEL / 32, NLAYER), tb, 0, s2>>>(Wk, hWk, DMODEL, KVD);
    w_t_h_kernel<<<dim3(KVD / 32,    DMODEL / 32, NLAYER), tb, 0, s2>>>(Wv, hWv, DMODEL, KVD);
    cudaEventRecord(ev1, s2);
    rmsnorm_kernel<<<M_TOK, 256>>>(x, an, h, nullptr);
    cudaStreamWaitEvent(0, ev1, 0);
    qkv_gemm_kernel<<<gQKV, 128, GEMM_SMEM>>>(h, hWq, hWk, hWv, q, k, v, cosT, sinT);
    w_t_h_kernel<<<dim3(DMODEL / 32, DMODEL / 32, NLAYER), tb, 0, s2>>>(Wo, hWo, DMODEL, DMODEL);
    w_t_h_kernel<<<dim3(FFDIM / 32,  DMODEL / 32, NLAYER), tb, 0, s2>>>(w0, hw0, DMODEL, FFDIM);
    w_t_h_kernel<<<dim3(FFDIM / 32,  DMODEL / 32, NLAYER), tb, 0, s2>>>(w1, hw1, DMODEL, FFDIM);
    w_t_h_kernel<<<dim3(DMODEL / 32, FFDIM / 32,  NLAYER), tb, 0, s2>>>(w2, hw2, FFDIM, DMODEL);
    cudaEventRecord(ev2, s2);

    flash_f16_kernel<<<dim3(S_LEN / 64, BATCH * NH), 128, FLASH_SMEM>>>(q, k, v, att);
    cudaStreamWaitEvent(0, ev2, 0);

    const float* xin = x;
    for (int l = 0; l < NLAYER; l++) {
        __half* hWq_l = hWq + (size_t)l * DMODEL * DMODEL;
        __half* hWk_l = hWk + (size_t)l * KVD * DMODEL;
        __half* hWv_l = hWv + (size_t)l * KVD * DMODEL;
        __half* hWo_l = hWo + (size_t)l * DMODEL * DMODEL;
        __half* hw0_l = hw0 + (size_t)l * FFDIM * DMODEL;
        __half* hw1_l = hw1 + (size_t)l * FFDIM * DMODEL;
        __half* hw2_l = hw2 + (size_t)l * DMODEL * FFDIM;

        if (l > 0) {
            rmsnorm_kernel<<<M_TOK, 256>>>(xin, an + l * DMODEL, h, nullptr);
            qkv_gemm_kernel<<<gQKV, 128, GEMM_SMEM>>>(h, hWq_l, hWk_l, hWv_l,
                                                      q, k, v, cosT, sinT);
            flash_f16_kernel<<<dim3(S_LEN / 64, BATCH * NH), 128, FLASH_SMEM>>>(q, k, v, att);
        }
        gemm_f16_kernel<<<gN768, 128, GEMM_SMEM>>>(att, hWo_l, hWo_l, xin, x1, x1, DMODEL, DMODEL, 3);
        rmsnorm_kernel<<<M_TOK, 256>>>(x1, sn + l * DMODEL, h, nullptr);
        gemm_f16_kernel<<<gFF2, 128, GEMM_SMEM>>>(h, hw0_l, hw1_l, nullptr, gate, gate2, FFDIM, DMODEL, 5);
        gemm_gate_kernel<<<gN768, 128, GATE_SMEM>>>(gate, gate2, hw2_l, x1, x2, DMODEL, FFDIM);
        xin = x2;
    }
    rmsnorm_kernel<<<M_TOK, 256>>>(x2, on, nullptr, out);
}